// round 10
// baseline (speedup 1.0000x reference)
#include <cuda_runtime.h>
#include <cstdint>

// Problem constants (fixed shapes from reference setup_inputs):
//   x, out_ae : (16, 3, 512, 512) fp32
//   out_seg   : (16, 1, 512, 512) fp32
//   out       : scalar fp32 loss
#define N_      16
#define C_      3
#define HW_     (512 * 512)              // 262144 floats per plane
#define NHW_    (N_ * HW_)               // 4194304 (pos+neg total)
#define BF_THRESH 0.5f

// ---- bulk-async pipeline geometry ----
#define TILE_FLOATS 2048                 // per-stream floats per tile
#define TILE_BYTES  (TILE_FLOATS * 4)    // 8192 B
#define TILES_PER_PLANE (HW_ / TILE_FLOATS)   // 128
#define NTILES      (NHW_ / TILE_FLOATS)      // 2048
#define NSTAGES     3
#define BUFS_PER_STAGE 7                 // seg, x0..x2, ae0..ae2
#define STAGE_BYTES (BUFS_PER_STAGE * TILE_BYTES)   // 57344
#define SMEM_DATA_OFF 1024               // mbarriers live below this
#define SMEM_DYN_BYTES (SMEM_DATA_OFF + NSTAGES * STAGE_BYTES)  // 173056

#define BLOCK_THREADS 512                // == TILE_FLOATS/4 : one float4/thread/buffer
#define GRID_BLOCKS   148                // persistent: one block per SM

// Device-global accumulators; finalizing block resets them each replay.
__device__ float        g_pos_sum = 0.0f;
__device__ float        g_tot_sum = 0.0f;
__device__ float        g_pos_cnt = 0.0f;
__device__ unsigned int g_done    = 0u;

__device__ __forceinline__ uint32_t smem_u32(const void* p) {
    uint32_t a;
    asm("{ .reg .u64 t; cvta.to.shared.u64 t, %1; cvt.u32.u64 %0, t; }"
        : "=r"(a) : "l"(p));
    return a;
}

__device__ __forceinline__ void mbar_init(uint32_t addr, uint32_t count) {
    asm volatile("mbarrier.init.shared.b64 [%0], %1;" :: "r"(addr), "r"(count) : "memory");
}

__device__ __forceinline__ void mbar_expect_tx(uint32_t addr, uint32_t bytes) {
    asm volatile("mbarrier.arrive.expect_tx.shared.b64 _, [%0], %1;"
                 :: "r"(addr), "r"(bytes) : "memory");
}

__device__ __forceinline__ void mbar_wait(uint32_t addr, uint32_t parity) {
    asm volatile(
        "{\n\t"
        ".reg .pred P;\n\t"
        "WAIT_%=:\n\t"
        "mbarrier.try_wait.parity.acquire.cta.shared::cta.b64 P, [%0], %1, 0x989680;\n\t"
        "@P bra.uni DONE_%=;\n\t"
        "bra.uni WAIT_%=;\n\t"
        "DONE_%=:\n\t"
        "}"
        :: "r"(addr), "r"(parity) : "memory");
}

__device__ __forceinline__ void bulk_ld(uint32_t smem_dst, const void* gmem_src,
                                        uint32_t bytes, uint32_t mbar) {
    asm volatile(
        "cp.async.bulk.shared::cluster.global.mbarrier::complete_tx::bytes "
        "[%0], [%1], %2, [%3];"
        :: "r"(smem_dst), "l"(gmem_src), "r"(bytes), "r"(mbar) : "memory");
}

__global__ __launch_bounds__(BLOCK_THREADS, 1)
void wmse_bulk_kernel(const float* __restrict__ x,
                      const float* __restrict__ ae,
                      const float* __restrict__ seg,
                      float* __restrict__ out)
{
    extern __shared__ __align__(128) char smem[];
    const int tid = threadIdx.x;
    const int bid = blockIdx.x;
    const uint32_t smem_base = smem_u32(smem);
    const uint32_t mbar0     = smem_base;                  // NSTAGES x 8 B
    const uint32_t data0     = smem_base + SMEM_DATA_OFF;

    if (tid == 0) {
        #pragma unroll
        for (int s = 0; s < NSTAGES; ++s) mbar_init(mbar0 + s * 8, 1);
    }
    __syncthreads();

    // Tiles for this block: bid, bid+148, ...  (NTILES = 2048)
    const int myN = (bid < NTILES) ? ((NTILES - 1 - bid) / GRID_BLOCKS + 1) : 0;

    // Issue all 7 bulk copies for this block's k-th tile into stage k%NSTAGES.
    auto issue = [&](int k) {
        const int tile = bid + k * GRID_BLOCKS;
        const int s    = k % NSTAGES;
        const uint32_t st = data0 + (uint32_t)s * STAGE_BYTES;
        const uint32_t mb = mbar0 + s * 8;
        mbar_expect_tx(mb, STAGE_BYTES);

        const int n    = tile >> 7;                        // tile / TILES_PER_PLANE
        const int inpl = (tile & (TILES_PER_PLANE - 1)) * TILE_FLOATS;

        bulk_ld(st, seg + (size_t)tile * TILE_FLOATS, TILE_BYTES, mb);
        #pragma unroll
        for (int c = 0; c < C_; ++c) {
            const size_t po = (size_t)(n * C_ + c) * HW_ + inpl;
            bulk_ld(st + (1 + c) * TILE_BYTES, x  + po, TILE_BYTES, mb);
            bulk_ld(st + (4 + c) * TILE_BYTES, ae + po, TILE_BYTES, mb);
        }
    };

    // Prologue: fill all stages.
    if (tid == 0) {
        const int pro = myN < NSTAGES ? myN : NSTAGES;
        for (int k = 0; k < pro; ++k) issue(k);
    }

    float pos_s = 0.0f, tot_s = 0.0f, cnt = 0.0f;

    for (int k = 0; k < myN; ++k) {
        const int s      = k % NSTAGES;
        const int parity = (k / NSTAGES) & 1;
        mbar_wait(mbar0 + s * 8, parity);

        const char* stg = smem + SMEM_DATA_OFF + (size_t)s * STAGE_BYTES;
        const float4 sv  = ((const float4*)(stg + 0 * TILE_BYTES))[tid];
        const float4 xv0 = ((const float4*)(stg + 1 * TILE_BYTES))[tid];
        const float4 xv1 = ((const float4*)(stg + 2 * TILE_BYTES))[tid];
        const float4 xv2 = ((const float4*)(stg + 3 * TILE_BYTES))[tid];
        const float4 av0 = ((const float4*)(stg + 4 * TILE_BYTES))[tid];
        const float4 av1 = ((const float4*)(stg + 5 * TILE_BYTES))[tid];
        const float4 av2 = ((const float4*)(stg + 6 * TILE_BYTES))[tid];

        const float px = sv.x > BF_THRESH ? 1.0f : 0.0f;
        const float py = sv.y > BF_THRESH ? 1.0f : 0.0f;
        const float pz = sv.z > BF_THRESH ? 1.0f : 0.0f;
        const float pw = sv.w > BF_THRESH ? 1.0f : 0.0f;
        cnt += (px + py) + (pz + pw);

        #define ACC(av, xv)                                                   \
        {                                                                     \
            const float dx = (av).x - (xv).x, dy = (av).y - (xv).y;           \
            const float dz = (av).z - (xv).z, dw = (av).w - (xv).w;           \
            const float ex = dx * dx, ey = dy * dy;                           \
            const float ez = dz * dz, ew = dw * dw;                           \
            tot_s += (ex + ey) + (ez + ew);                                   \
            pos_s += (ex * px + ey * py) + (ez * pz + ew * pw);               \
        }
        ACC(av0, xv0)
        ACC(av1, xv1)
        ACC(av2, xv2)
        #undef ACC

        __syncthreads();   // all threads done reading stage s -> safe to refill
        if (tid == 0 && (k + NSTAGES) < myN) issue(k + NSTAGES);
    }

    // ---- intra-warp reduction ----
    #pragma unroll
    for (int o = 16; o > 0; o >>= 1) {
        pos_s += __shfl_down_sync(0xFFFFFFFFu, pos_s, o);
        tot_s += __shfl_down_sync(0xFFFFFFFFu, tot_s, o);
        cnt   += __shfl_down_sync(0xFFFFFFFFu, cnt,   o);
    }

    // ---- intra-block reduction (16 warps) ----
    __shared__ float sp[16], st_[16], sc[16];
    const int wid  = tid >> 5;
    const int lane = tid & 31;
    if (lane == 0) { sp[wid] = pos_s; st_[wid] = tot_s; sc[wid] = cnt; }
    __syncthreads();

    if (tid == 0) {
        float bp = 0.0f, bt = 0.0f, bc = 0.0f;
        #pragma unroll
        for (int i = 0; i < BLOCK_THREADS / 32; ++i) {
            bp += sp[i]; bt += st_[i]; bc += sc[i];
        }

        atomicAdd(&g_pos_sum, bp);
        atomicAdd(&g_tot_sum, bt);
        atomicAdd(&g_pos_cnt, bc);
        __threadfence();

        const unsigned int ticket = atomicAdd(&g_done, 1u);
        if (ticket == GRID_BLOCKS - 1u) {
            const float ps = atomicAdd(&g_pos_sum, 0.0f);
            const float ts = atomicAdd(&g_tot_sum, 0.0f);
            const float pn = atomicAdd(&g_pos_cnt, 0.0f);

            const float total     = (float)NHW_;
            const float neg_num   = total - pn;
            const float pos_ratio = pn / total;
            const float neg_ratio = 1.0f - pos_ratio;
            const float cf        = (float)C_;
            const float mse_pos   = ps / (pn * cf);
            const float mse_neg   = (ts - ps) / (neg_num * cf);
            out[0] = pos_ratio * mse_neg + neg_ratio * mse_pos;

            // Reset accumulators so the next graph replay starts clean.
            g_pos_sum = 0.0f;
            g_tot_sum = 0.0f;
            g_pos_cnt = 0.0f;
            __threadfence();
            g_done = 0u;
        }
    }
}

extern "C" void kernel_launch(void* const* d_in, const int* in_sizes, int n_in,
                              void* d_out, int out_size)
{
    const float* x   = (const float*)d_in[0];   // x        (16,3,512,512)
    const float* ae  = (const float*)d_in[1];   // out_ae   (16,3,512,512)
    const float* seg = (const float*)d_in[2];   // out_seg  (16,1,512,512)
    float* out = (float*)d_out;

    // 173,056 B dynamic smem: needs opt-in above the 48 KB default.
    cudaFuncSetAttribute(wmse_bulk_kernel,
                         cudaFuncAttributeMaxDynamicSharedMemorySize,
                         SMEM_DYN_BYTES);

    wmse_bulk_kernel<<<GRID_BLOCKS, BLOCK_THREADS, SMEM_DYN_BYTES>>>(x, ae, seg, out);
}

// round 12
// speedup vs baseline: 1.0028x; 1.0028x over previous
#include <cuda_runtime.h>

// Problem constants (fixed shapes from reference setup_inputs):
//   x, out_ae : (16, 3, 512, 512) fp32
//   out_seg   : (16, 1, 512, 512) fp32
//   out       : scalar fp32 loss
#define N_      16
#define C_      3
#define HW_     (512 * 512)          // 262144
#define NHW_    (N_ * HW_)           // 4194304  (pos+neg total over (n,1,h,w))
#define HW4_    (HW_ / 4)            // 65536    (float4 units per plane)
#define NHW4_   (NHW_ / 4)           // 1048576  (float4 work items)
#define BF_THRESH 0.5f

#define BLOCK_THREADS 256
// COMPILE with the R6-proven launch_bounds (256, 4): 64-reg budget, ptxas
// produces 46 regs and keeps all 7 LDG.128 dests live (MLP=7).
// LAUNCH 5 blocks/SM: at 46 regs the RF fits 5 blocks (5*256*46 = 58.9K <= 64K),
// so grid 740 gives a single resident wave of 40 warps/SM — more latency
// tolerance than R6's 592 without touching the compile (R7 showed recompiling
// at (256,5) flips ptxas's scheduler and destroys the load batch).
#define GRID_BLOCKS   740            // 148 SMs x 5 resident blocks

// Device-global accumulators. Zero-initialized at module load; the
// finalizing block resets them so every graph replay starts clean.
__device__ float        g_pos_sum = 0.0f;
__device__ float        g_tot_sum = 0.0f;
__device__ float        g_pos_cnt = 0.0f;
__device__ unsigned int g_done    = 0u;

__global__ __launch_bounds__(BLOCK_THREADS, 4)   // DO NOT change: 64-reg budget
void wmse_kernel(const float4* __restrict__ x4,
                 const float4* __restrict__ ae4,
                 const float4* __restrict__ seg4,
                 float* __restrict__ out)
{
    float pos_s = 0.0f;   // sum of diff^2 where seg > 0.5 (over all c)
    float tot_s = 0.0f;   // sum of diff^2 over everything
    float cnt   = 0.0f;   // count of seg > 0.5 (over n,h,w only)

    const int stride = GRID_BLOCKS * BLOCK_THREADS;   // 189440
    for (int g = blockIdx.x * BLOCK_THREADS + threadIdx.x; g < NHW4_; g += stride) {
        // g indexes float4 groups over (n, h*w/4). HW4_ = 65536 = 2^16.
        const int n    = g >> 16;
        const int hwq  = g & 0xFFFF;
        const int base = n * (C_ * HW4_) + hwq;

        // ---- issue ALL 7 independent loads first (front-batched MLP) ----
        const float4 s   = seg4[g];
        const float4 xv0 = x4 [base + 0 * HW4_];
        const float4 av0 = ae4[base + 0 * HW4_];
        const float4 xv1 = x4 [base + 1 * HW4_];
        const float4 av1 = ae4[base + 1 * HW4_];
        const float4 xv2 = x4 [base + 2 * HW4_];
        const float4 av2 = ae4[base + 2 * HW4_];

        // ---- then compute ----
        const float px = s.x > BF_THRESH ? 1.0f : 0.0f;
        const float py = s.y > BF_THRESH ? 1.0f : 0.0f;
        const float pz = s.z > BF_THRESH ? 1.0f : 0.0f;
        const float pw = s.w > BF_THRESH ? 1.0f : 0.0f;
        cnt += (px + py) + (pz + pw);

        {
            const float dx = av0.x - xv0.x, dy = av0.y - xv0.y;
            const float dz = av0.z - xv0.z, dw = av0.w - xv0.w;
            const float ex = dx * dx, ey = dy * dy, ez = dz * dz, ew = dw * dw;
            tot_s += (ex + ey) + (ez + ew);
            pos_s += (ex * px + ey * py) + (ez * pz + ew * pw);
        }
        {
            const float dx = av1.x - xv1.x, dy = av1.y - xv1.y;
            const float dz = av1.z - xv1.z, dw = av1.w - xv1.w;
            const float ex = dx * dx, ey = dy * dy, ez = dz * dz, ew = dw * dw;
            tot_s += (ex + ey) + (ez + ew);
            pos_s += (ex * px + ey * py) + (ez * pz + ew * pw);
        }
        {
            const float dx = av2.x - xv2.x, dy = av2.y - xv2.y;
            const float dz = av2.z - xv2.z, dw = av2.w - xv2.w;
            const float ex = dx * dx, ey = dy * dy, ez = dz * dz, ew = dw * dw;
            tot_s += (ex + ey) + (ez + ew);
            pos_s += (ex * px + ey * py) + (ez * pz + ew * pw);
        }
    }

    // ---- intra-warp reduction ----
    #pragma unroll
    for (int o = 16; o > 0; o >>= 1) {
        pos_s += __shfl_down_sync(0xFFFFFFFFu, pos_s, o);
        tot_s += __shfl_down_sync(0xFFFFFFFFu, tot_s, o);
        cnt   += __shfl_down_sync(0xFFFFFFFFu, cnt,   o);
    }

    // ---- intra-block reduction (8 warps) ----
    __shared__ float sp[8], st[8], sc[8];
    const int wid = threadIdx.x >> 5;
    const int lid = threadIdx.x & 31;
    if (lid == 0) { sp[wid] = pos_s; st[wid] = tot_s; sc[wid] = cnt; }
    __syncthreads();

    if (threadIdx.x == 0) {
        float bp = 0.0f, bt = 0.0f, bc = 0.0f;
        #pragma unroll
        for (int i = 0; i < BLOCK_THREADS / 32; ++i) {
            bp += sp[i]; bt += st[i]; bc += sc[i];
        }

        atomicAdd(&g_pos_sum, bp);
        atomicAdd(&g_tot_sum, bt);
        atomicAdd(&g_pos_cnt, bc);
        __threadfence();

        const unsigned int ticket = atomicAdd(&g_done, 1u);
        if (ticket == GRID_BLOCKS - 1u) {
            // Last block: all partials globally visible (threadfence + atomic order).
            const float ps = atomicAdd(&g_pos_sum, 0.0f);
            const float ts = atomicAdd(&g_tot_sum, 0.0f);
            const float pn = atomicAdd(&g_pos_cnt, 0.0f);

            const float total     = (float)NHW_;
            const float neg_num   = total - pn;
            const float pos_ratio = pn / total;
            const float neg_ratio = 1.0f - pos_ratio;
            const float cf        = (float)C_;
            const float mse_pos   = ps / (pn * cf);
            const float mse_neg   = (ts - ps) / (neg_num * cf);
            out[0] = pos_ratio * mse_neg + neg_ratio * mse_pos;

            // Reset accumulators so the next graph replay starts clean.
            g_pos_sum = 0.0f;
            g_tot_sum = 0.0f;
            g_pos_cnt = 0.0f;
            __threadfence();
            g_done = 0u;
        }
    }
}

extern "C" void kernel_launch(void* const* d_in, const int* in_sizes, int n_in,
                              void* d_out, int out_size)
{
    const float4* x4   = (const float4*)d_in[0];   // x        (16,3,512,512)
    const float4* ae4  = (const float4*)d_in[1];   // out_ae   (16,3,512,512)
    const float4* seg4 = (const float4*)d_in[2];   // out_seg  (16,1,512,512)
    float* out = (float*)d_out;

    wmse_kernel<<<GRID_BLOCKS, BLOCK_THREADS>>>(x4, ae4, seg4, out);
}

// round 14
// speedup vs baseline: 1.0227x; 1.0198x over previous
#include <cuda_runtime.h>

// Problem constants (fixed shapes from reference setup_inputs):
//   x, out_ae : (16, 3, 512, 512) fp32
//   out_seg   : (16, 1, 512, 512) fp32
//   out       : scalar fp32 loss
#define N_      16
#define C_      3
#define HW_     (512 * 512)          // 262144
#define NHW_    (N_ * HW_)           // 4194304  (pos+neg total over (n,1,h,w))
#define HW4_    (HW_ / 4)            // 65536    (float4 units per plane)
#define NHW4_   (NHW_ / 4)           // 1048576  (float4 work items) = 2^20
#define BF_THRESH 0.5f

// Perfectly balanced geometry: 1024 blocks x 128 threads = 131072 threads,
// each doing EXACTLY 8 iterations (2^20 / 131072 = 8). No ragged tail, no
// end-of-loop partial wave. Block distribution across 148 SMs: 136x7 + 12x6.
#define BLOCK_THREADS 128
#define GRID_BLOCKS   1024
#define ITERS         8
#define STRIDE        (GRID_BLOCKS * BLOCK_THREADS)   // 131072

// Device-global accumulators. Zero-initialized at module load; the
// finalizing block resets them so every graph replay starts clean.
__device__ float        g_pos_sum = 0.0f;
__device__ float        g_tot_sum = 0.0f;
__device__ float        g_pos_cnt = 0.0f;
__device__ unsigned int g_done    = 0u;

// (128, 8) -> 64-reg/thread budget, identical to the proven (256, 4) budget
// that yields 46 regs and a fully front-batched 7-load body. Do not tighten.
__global__ __launch_bounds__(BLOCK_THREADS, 8)
void wmse_kernel(const float4* __restrict__ x4,
                 const float4* __restrict__ ae4,
                 const float4* __restrict__ seg4,
                 float* __restrict__ out)
{
    float pos_s = 0.0f;   // sum of diff^2 where seg > 0.5 (over all c)
    float tot_s = 0.0f;   // sum of diff^2 over everything
    float cnt   = 0.0f;   // count of seg > 0.5 (over n,h,w only)

    int g = blockIdx.x * BLOCK_THREADS + threadIdx.x;

    #pragma unroll 1      // keep the single-iteration body; do NOT unroll 8x
    for (int it = 0; it < ITERS; ++it, g += STRIDE) {
        // g indexes float4 groups over (n, h*w/4). HW4_ = 65536 = 2^16.
        const int n    = g >> 16;
        const int hwq  = g & 0xFFFF;
        const int base = n * (C_ * HW4_) + hwq;

        // ---- issue ALL 7 independent loads first (front-batched MLP) ----
        const float4 s   = seg4[g];
        const float4 xv0 = x4 [base + 0 * HW4_];
        const float4 av0 = ae4[base + 0 * HW4_];
        const float4 xv1 = x4 [base + 1 * HW4_];
        const float4 av1 = ae4[base + 1 * HW4_];
        const float4 xv2 = x4 [base + 2 * HW4_];
        const float4 av2 = ae4[base + 2 * HW4_];

        // ---- then compute ----
        const float px = s.x > BF_THRESH ? 1.0f : 0.0f;
        const float py = s.y > BF_THRESH ? 1.0f : 0.0f;
        const float pz = s.z > BF_THRESH ? 1.0f : 0.0f;
        const float pw = s.w > BF_THRESH ? 1.0f : 0.0f;
        cnt += (px + py) + (pz + pw);

        {
            const float dx = av0.x - xv0.x, dy = av0.y - xv0.y;
            const float dz = av0.z - xv0.z, dw = av0.w - xv0.w;
            const float ex = dx * dx, ey = dy * dy, ez = dz * dz, ew = dw * dw;
            tot_s += (ex + ey) + (ez + ew);
            pos_s += (ex * px + ey * py) + (ez * pz + ew * pw);
        }
        {
            const float dx = av1.x - xv1.x, dy = av1.y - xv1.y;
            const float dz = av1.z - xv1.z, dw = av1.w - xv1.w;
            const float ex = dx * dx, ey = dy * dy, ez = dz * dz, ew = dw * dw;
            tot_s += (ex + ey) + (ez + ew);
            pos_s += (ex * px + ey * py) + (ez * pz + ew * pw);
        }
        {
            const float dx = av2.x - xv2.x, dy = av2.y - xv2.y;
            const float dz = av2.z - xv2.z, dw = av2.w - xv2.w;
            const float ex = dx * dx, ey = dy * dy, ez = dz * dz, ew = dw * dw;
            tot_s += (ex + ey) + (ez + ew);
            pos_s += (ex * px + ey * py) + (ez * pz + ew * pw);
        }
    }

    // ---- intra-warp reduction ----
    #pragma unroll
    for (int o = 16; o > 0; o >>= 1) {
        pos_s += __shfl_down_sync(0xFFFFFFFFu, pos_s, o);
        tot_s += __shfl_down_sync(0xFFFFFFFFu, tot_s, o);
        cnt   += __shfl_down_sync(0xFFFFFFFFu, cnt,   o);
    }

    // ---- intra-block reduction (4 warps) ----
    __shared__ float sp[4], st[4], sc[4];
    const int wid = threadIdx.x >> 5;
    const int lid = threadIdx.x & 31;
    if (lid == 0) { sp[wid] = pos_s; st[wid] = tot_s; sc[wid] = cnt; }
    __syncthreads();

    if (threadIdx.x == 0) {
        float bp = 0.0f, bt = 0.0f, bc = 0.0f;
        #pragma unroll
        for (int i = 0; i < BLOCK_THREADS / 32; ++i) {
            bp += sp[i]; bt += st[i]; bc += sc[i];
        }

        atomicAdd(&g_pos_sum, bp);
        atomicAdd(&g_tot_sum, bt);
        atomicAdd(&g_pos_cnt, bc);
        __threadfence();

        const unsigned int ticket = atomicAdd(&g_done, 1u);
        if (ticket == GRID_BLOCKS - 1u) {
            // Last block: all partials globally visible (threadfence + atomic order).
            const float ps = atomicAdd(&g_pos_sum, 0.0f);
            const float ts = atomicAdd(&g_tot_sum, 0.0f);
            const float pn = atomicAdd(&g_pos_cnt, 0.0f);

            const float total     = (float)NHW_;
            const float neg_num   = total - pn;
            const float pos_ratio = pn / total;
            const float neg_ratio = 1.0f - pos_ratio;
            const float cf        = (float)C_;
            const float mse_pos   = ps / (pn * cf);
            const float mse_neg   = (ts - ps) / (neg_num * cf);
            out[0] = pos_ratio * mse_neg + neg_ratio * mse_pos;

            // Reset accumulators so the next graph replay starts clean.
            g_pos_sum = 0.0f;
            g_tot_sum = 0.0f;
            g_pos_cnt = 0.0f;
            __threadfence();
            g_done = 0u;
        }
    }
}

extern "C" void kernel_launch(void* const* d_in, const int* in_sizes, int n_in,
                              void* d_out, int out_size)
{
    const float4* x4   = (const float4*)d_in[0];   // x        (16,3,512,512)
    const float4* ae4  = (const float4*)d_in[1];   // out_ae   (16,3,512,512)
    const float4* seg4 = (const float4*)d_in[2];   // out_seg  (16,1,512,512)
    float* out = (float*)d_out;

    wmse_kernel<<<GRID_BLOCKS, BLOCK_THREADS>>>(x4, ae4, seg4, out);
}